// round 6
// baseline (speedup 1.0000x reference)
#include <cuda_runtime.h>
#include <float.h>

#define BATCH 8
#define CCH   192
#define OUTC  384
#define NPTS  3136
#define KNN   16
#define ROWS  (BATCH*NPTS)   /* 25088 */
#define TWO_C 384
#define NPART 196            /* 25088/128 row-partials for BN */

// ---------------- scratch (static device globals; no allocation) -------------
__device__ __align__(16) float g_xt[(size_t)BATCH*NPTS*CCH];     // (B,N,C)
__device__ float g_x2[ROWS];
__device__ __align__(16) float g_feat[(size_t)ROWS*TWO_C];       // (B*N,2C)
__device__ __align__(16) float g_y[(size_t)ROWS*OUTC];           // (B*N,OUT)
__device__ float g_psum[NPART*OUTC];
__device__ float g_psq [NPART*OUTC];
__device__ float g_scale[OUTC];
__device__ float g_shift[OUTC];

// ---------------- K1: (B,C,N) -> (B,N,C) tiled transpose ---------------------
__global__ void k_transpose(const float* __restrict__ x) {
    __shared__ float sT[32][33];
    int b = blockIdx.z;
    int n0 = blockIdx.x * 32;
    int c0 = blockIdx.y * 32;
    int tx = threadIdx.x, ty = threadIdx.y;
    const float* xb = x + (size_t)b * CCH * NPTS;
#pragma unroll
    for (int q = 0; q < 4; q++) {
        int c = c0 + ty + 8*q;
        sT[ty + 8*q][tx] = xb[(size_t)c * NPTS + n0 + tx];
    }
    __syncthreads();
    float* xtb = g_xt + (size_t)b * NPTS * CCH;
#pragma unroll
    for (int q = 0; q < 4; q++) {
        int n = n0 + ty + 8*q;
        xtb[(size_t)n * CCH + c0 + tx] = sT[tx][ty + 8*q];
    }
}

// ---------------- K1b: squared norms per point -------------------------------
__global__ void k_x2() {
    int row  = blockIdx.x * 8 + (threadIdx.x >> 5);
    int lane = threadIdx.x & 31;
    const float* r = g_xt + (size_t)row * CCH;
    float s = 0.f;
#pragma unroll
    for (int c = lane; c < CCH; c += 32) { float v = r[c]; s = fmaf(v, v, s); }
#pragma unroll
    for (int o = 16; o; o >>= 1) s += __shfl_down_sync(0xffffffffu, s, o);
    if (lane == 0) g_x2[row] = s;
}

// Lexicographic (val, idx) top-K insert; order-independent selection, matches
// top_k tie semantics (equal values -> smaller index preferred).
#define TOPK_INS(TV,TI,WV,WI,WS,SS,JG) do{ \
  if ((SS) < (WV) || ((SS) == (WV) && (JG) < (WI))) { \
    _Pragma("unroll") for (int _k=0;_k<KNN;_k++) if (_k==(WS)){TV[_k]=(SS);TI[_k]=(JG);} \
    (WV)=-FLT_MAX;(WI)=-1; \
    _Pragma("unroll") for (int _k=0;_k<KNN;_k++) \
      if (TV[_k]>(WV) || (TV[_k]==(WV) && TI[_k]>(WI))){(WV)=TV[_k];(WI)=TI[_k];(WS)=_k;} \
  } }while(0)

// ---------------- K2: fused distance-GEMM + top-K + maxrel + feat ------------
// 256 threads / 32 query rows / j-tiles of 128 candidates. Candidate tiles come
// straight from x (B,C,N): already k-major -> no transpose, float4 everywhere.
// score_j = x2[j] - 2*<x_i,x_j>, ascending-k fmaf chain (bitwise == prev round).
__global__ void __launch_bounds__(256, 2) k_knn_feat(const float* __restrict__ x) {
    extern __shared__ float sm[];
    float* sXi = sm;                    // 32*193 = 6176
    float* sXj = sm + 6176;             // 2 buffers * 32*132 = 8448
    float* sx2 = sm + 6176 + 8448;      // 128
    int*   sTop = (int*)(sx2 + 128);    // 32*16 = 512

    int b = blockIdx.y;
    int ibase = blockIdx.x * 32;
    const float* xb  = x    + (size_t)b * CCH * NPTS;
    const float* xtb = g_xt + (size_t)b * NPTS * CCH;
    const float* x2b = g_x2 + b * NPTS;

    int t  = threadIdx.x;
    int tx = t & 15, ty = t >> 4;
    int i0 = ty*2, i1 = i0 + 1;
    int jc = tx*8;
    int row_s = t >> 3, sl = t & 7;

    // query rows (coalesced from g_xt)
#pragma unroll
    for (int q = 0; q < 24; q++) {
        int idx = t + q*256;
        int i = idx / CCH, c = idx % CCH;
        sXi[i*193 + c] = xtb[(size_t)(ibase + i)*CCH + c];
    }

    float tv[KNN]; int ti[KNN];
    float wv = FLT_MAX; int wi = 0x7fffffff; int ws = 0;
#pragma unroll
    for (int k = 0; k < KNN; k++) { tv[k] = FLT_MAX; ti[k] = 0x7fffffff; }

    for (int tile = 0; tile < 25; tile++) {
        int jb = tile * 128;
        __syncthreads();   // prev-tile scan / sXi load complete
        if (t < 128) sx2[t] = (jb + t < NPTS) ? x2b[jb + t] : 0.f;

        float4 pf[4];
        // chunk 0: load + store to buffer 0
#pragma unroll
        for (int it = 0; it < 4; it++) {
            int idx = t + it*256;
            int k = idx >> 5, j4 = (idx & 31)*4;
            pf[it] = (jb + j4 < NPTS) ? *(const float4*)(xb + (size_t)k*NPTS + jb + j4)
                                      : make_float4(0.f,0.f,0.f,0.f);
        }
#pragma unroll
        for (int it = 0; it < 4; it++) {
            int idx = t + it*256;
            int k = idx >> 5, j4 = (idx & 31)*4;
            *(float4*)&sXj[k*132 + j4] = pf[it];
        }
        __syncthreads();

        float acc[2][8];
#pragma unroll
        for (int r = 0; r < 2; r++)
#pragma unroll
            for (int w2 = 0; w2 < 8; w2++) acc[r][w2] = 0.f;

        int buf = 0;
        for (int c = 0; c < 6; c++) {
            if (c < 5) {
#pragma unroll
                for (int it = 0; it < 4; it++) {
                    int idx = t + it*256;
                    int k = idx >> 5, j4 = (idx & 31)*4;
                    pf[it] = (jb + j4 < NPTS)
                        ? *(const float4*)(xb + (size_t)((c+1)*32 + k)*NPTS + jb + j4)
                        : make_float4(0.f,0.f,0.f,0.f);
                }
            }
            const float* Bm = sXj + buf*4224;
#pragma unroll
            for (int k = 0; k < 32; k++) {
                float a0 = sXi[i0*193 + c*32 + k];
                float a1 = sXi[i1*193 + c*32 + k];
                float4 b0 = *(const float4*)&Bm[k*132 + jc];
                float4 b1 = *(const float4*)&Bm[k*132 + jc + 4];
                acc[0][0]=fmaf(a0,b0.x,acc[0][0]); acc[0][1]=fmaf(a0,b0.y,acc[0][1]);
                acc[0][2]=fmaf(a0,b0.z,acc[0][2]); acc[0][3]=fmaf(a0,b0.w,acc[0][3]);
                acc[0][4]=fmaf(a0,b1.x,acc[0][4]); acc[0][5]=fmaf(a0,b1.y,acc[0][5]);
                acc[0][6]=fmaf(a0,b1.z,acc[0][6]); acc[0][7]=fmaf(a0,b1.w,acc[0][7]);
                acc[1][0]=fmaf(a1,b0.x,acc[1][0]); acc[1][1]=fmaf(a1,b0.y,acc[1][1]);
                acc[1][2]=fmaf(a1,b0.z,acc[1][2]); acc[1][3]=fmaf(a1,b0.w,acc[1][3]);
                acc[1][4]=fmaf(a1,b1.x,acc[1][4]); acc[1][5]=fmaf(a1,b1.y,acc[1][5]);
                acc[1][6]=fmaf(a1,b1.z,acc[1][6]); acc[1][7]=fmaf(a1,b1.w,acc[1][7]);
            }
            if (c < 5) {
                float* D = sXj + (buf^1)*4224;
#pragma unroll
                for (int it = 0; it < 4; it++) {
                    int idx = t + it*256;
                    int k = idx >> 5, j4 = (idx & 31)*4;
                    *(float4*)&D[k*132 + j4] = pf[it];
                }
                __syncthreads();
                buf ^= 1;
            }
        }
        // finalize scores into sXj half 0 (its chunk data is dead; half 1 is
        // still being read for chunk 5 by other threads -> disjoint)
        float* S0 = sXj;
#pragma unroll
        for (int r = 0; r < 2; r++) {
            int ir = r ? i1 : i0;
            float v[8];
#pragma unroll
            for (int w2 = 0; w2 < 8; w2++)
                v[w2] = (jb + jc + w2 < NPTS) ? (sx2[jc + w2] - 2.f*acc[r][w2]) : FLT_MAX;
            *(float4*)&S0[ir*132 + jc]     = make_float4(v[0],v[1],v[2],v[3]);
            *(float4*)&S0[ir*132 + jc + 4] = make_float4(v[4],v[5],v[6],v[7]);
        }
        __syncthreads();
        // parallel sliced scan: 8 threads per row, 16 candidates each
        int jgbase = jb + sl*16;
        if (jgbase < NPTS) {
            const float* srow = S0 + row_s*132 + sl*16;
#pragma unroll
            for (int q = 0; q < 16; q++) {
                float s = srow[q];
                int jg = jgbase + q;
                TOPK_INS(tv, ti, wv, wi, ws, s, jg);
            }
        }
    }
    __syncthreads();
    // merge: dump 8 local lists per row, one thread per row selects final 16
    float* sMv = sXj;                   // stride 129 (conflict-free)
    int*   sMi = (int*)(sXj + 4224);
#pragma unroll
    for (int q = 0; q < KNN; q++) {
        sMv[row_s*129 + sl*16 + q] = tv[q];
        sMi[row_s*129 + sl*16 + q] = ti[q];
    }
    __syncthreads();
    if (t < 32) {
        float bv[KNN]; int bi[KNN];
        float mwv = FLT_MAX; int mwi = 0x7fffffff; int mws = 0;
#pragma unroll
        for (int k = 0; k < KNN; k++) { bv[k] = FLT_MAX; bi[k] = 0x7fffffff; }
        for (int s = 0; s < 128; s++) {
            float sv = sMv[t*129 + s];
            int  si = sMi[t*129 + s];
            TOPK_INS(bv, bi, mwv, mwi, mws, sv, si);
        }
#pragma unroll
        for (int k = 0; k < KNN; k++) sTop[t*KNN + k] = bi[k];
    }
    __syncthreads();
    // gather neighbors, max-relative, interleaved feature write
    float2* featb = (float2*)g_feat + (size_t)(b*NPTS + ibase) * CCH;
#pragma unroll
    for (int q = 0; q < 24; q++) {
        int idx = t + q*256;
        int r = idx / CCH, c = idx % CCH;
        float xi = sXi[r*193 + c];
        float m = -FLT_MAX;
#pragma unroll
        for (int k = 0; k < KNN; k++) {
            int j = sTop[r*KNN + k];
            m = fmaxf(m, xtb[(size_t)j*CCH + c]);
        }
        featb[(size_t)r*CCH + c] = make_float2(xi, m - xi);
    }
}

// ---------------- K3: y = feat @ w^T + b, fused BN partial sums --------------
// 128(m) x 64(o) block tile, 8x4 microtile, all-float4 smem reads.
__global__ void __launch_bounds__(256) k_gemm(const float* __restrict__ w,
                                              const float* __restrict__ bias) {
    __shared__ float sA[32*132];   // [k][m]
    __shared__ float sB[32*68];    // [k][o]
    __shared__ float sPs[16*64];
    __shared__ float sPq[16*64];
    int r0 = blockIdx.x * 128;
    int o0 = blockIdx.y * 64;
    int t  = threadIdx.x;
    int tx = t & 15, ty = t >> 4;
    int oc = tx*4, mc = ty*8;
    float acc[8][4];
#pragma unroll
    for (int q = 0; q < 8; q++)
#pragma unroll
        for (int w2 = 0; w2 < 4; w2++) acc[q][w2] = 0.f;

    for (int kc = 0; kc < TWO_C; kc += 32) {
        __syncthreads();
#pragma unroll
        for (int it = 0; it < 4; it++) {
            int idx = t + it*256;
            int m = idx >> 3, kq = idx & 7;
            float4 v = *(const float4*)&g_feat[(size_t)(r0 + m)*TWO_C + kc + kq*4];
            sA[(kq*4+0)*132 + m] = v.x;
            sA[(kq*4+1)*132 + m] = v.y;
            sA[(kq*4+2)*132 + m] = v.z;
            sA[(kq*4+3)*132 + m] = v.w;
        }
#pragma unroll
        for (int it = 0; it < 2; it++) {
            int idx = t + it*256;
            int o = idx >> 3, kq = idx & 7;
            float4 v = *(const float4*)&w[(size_t)(o0 + o)*TWO_C + kc + kq*4];
            sB[(kq*4+0)*68 + o] = v.x;
            sB[(kq*4+1)*68 + o] = v.y;
            sB[(kq*4+2)*68 + o] = v.z;
            sB[(kq*4+3)*68 + o] = v.w;
        }
        __syncthreads();
#pragma unroll
        for (int k = 0; k < 32; k++) {
            float4 bv  = *(const float4*)&sB[k*68 + oc];
            float4 alo = *(const float4*)&sA[k*132 + mc];
            float4 ahi = *(const float4*)&sA[k*132 + mc + 4];
            acc[0][0]=fmaf(alo.x,bv.x,acc[0][0]); acc[0][1]=fmaf(alo.x,bv.y,acc[0][1]);
            acc[0][2]=fmaf(alo.x,bv.z,acc[0][2]); acc[0][3]=fmaf(alo.x,bv.w,acc[0][3]);
            acc[1][0]=fmaf(alo.y,bv.x,acc[1][0]); acc[1][1]=fmaf(alo.y,bv.y,acc[1][1]);
            acc[1][2]=fmaf(alo.y,bv.z,acc[1][2]); acc[1][3]=fmaf(alo.y,bv.w,acc[1][3]);
            acc[2][0]=fmaf(alo.z,bv.x,acc[2][0]); acc[2][1]=fmaf(alo.z,bv.y,acc[2][1]);
            acc[2][2]=fmaf(alo.z,bv.z,acc[2][2]); acc[2][3]=fmaf(alo.z,bv.w,acc[2][3]);
            acc[3][0]=fmaf(alo.w,bv.x,acc[3][0]); acc[3][1]=fmaf(alo.w,bv.y,acc[3][1]);
            acc[3][2]=fmaf(alo.w,bv.z,acc[3][2]); acc[3][3]=fmaf(alo.w,bv.w,acc[3][3]);
            acc[4][0]=fmaf(ahi.x,bv.x,acc[4][0]); acc[4][1]=fmaf(ahi.x,bv.y,acc[4][1]);
            acc[4][2]=fmaf(ahi.x,bv.z,acc[4][2]); acc[4][3]=fmaf(ahi.x,bv.w,acc[4][3]);
            acc[5][0]=fmaf(ahi.y,bv.x,acc[5][0]); acc[5][1]=fmaf(ahi.y,bv.y,acc[5][1]);
            acc[5][2]=fmaf(ahi.y,bv.z,acc[5][2]); acc[5][3]=fmaf(ahi.y,bv.w,acc[5][3]);
            acc[6][0]=fmaf(ahi.z,bv.x,acc[6][0]); acc[6][1]=fmaf(ahi.z,bv.y,acc[6][1]);
            acc[6][2]=fmaf(ahi.z,bv.z,acc[6][2]); acc[6][3]=fmaf(ahi.z,bv.w,acc[6][3]);
            acc[7][0]=fmaf(ahi.w,bv.x,acc[7][0]); acc[7][1]=fmaf(ahi.w,bv.y,acc[7][1]);
            acc[7][2]=fmaf(ahi.w,bv.z,acc[7][2]); acc[7][3]=fmaf(ahi.w,bv.w,acc[7][3]);
        }
    }
    // epilogue: +bias, store y, accumulate per-thread BN partials
    float4 bb = *(const float4*)&bias[o0 + oc];
    float ps[4] = {0,0,0,0}, pq[4] = {0,0,0,0};
#pragma unroll
    for (int q = 0; q < 8; q++) {
        float4 v;
        v.x = acc[q][0] + bb.x; v.y = acc[q][1] + bb.y;
        v.z = acc[q][2] + bb.z; v.w = acc[q][3] + bb.w;
        *(float4*)&g_y[(size_t)(r0 + mc + q)*OUTC + o0 + oc] = v;
        ps[0] += v.x; pq[0] = fmaf(v.x, v.x, pq[0]);
        ps[1] += v.y; pq[1] = fmaf(v.y, v.y, pq[1]);
        ps[2] += v.z; pq[2] = fmaf(v.z, v.z, pq[2]);
        ps[3] += v.w; pq[3] = fmaf(v.w, v.w, pq[3]);
    }
#pragma unroll
    for (int w2 = 0; w2 < 4; w2++) {
        sPs[ty*64 + oc + w2] = ps[w2];
        sPq[ty*64 + oc + w2] = pq[w2];
    }
    __syncthreads();
    if (t < 64) {
        float S = 0.f, Q = 0.f;
#pragma unroll
        for (int g = 0; g < 16; g++) { S += sPs[g*64 + t]; Q += sPq[g*64 + t]; }
        g_psum[blockIdx.x*OUTC + o0 + t] = S;
        g_psq [blockIdx.x*OUTC + o0 + t] = Q;
    }
}

// ---------------- K4b: finalize BN scale/shift -------------------------------
__global__ void k_stats(const float* __restrict__ gamma,
                        const float* __restrict__ beta) {
    int o = threadIdx.x;
    float S = 0.f, Q = 0.f;
    for (int p = 0; p < NPART; p++) { S += g_psum[p*OUTC + o]; Q += g_psq[p*OUTC + o]; }
    float inv  = 1.f / (float)ROWS;
    float mean = S * inv;
    float var  = Q * inv - mean*mean;
    float sc   = gamma[o] * rsqrtf(var + 1e-5f);
    g_scale[o] = sc;
    g_shift[o] = beta[o] - mean * sc;
}

// ---------------- K5: normalize + ReLU + transpose to (B,OUT,N) --------------
__global__ void k_out(float* __restrict__ out) {
    __shared__ float sT[32][33];
    int b  = blockIdx.z;
    int n0 = blockIdx.x * 32;
    int o0 = blockIdx.y * 32;
    int tx = threadIdx.x, ty = threadIdx.y;
    {
        int o = o0 + tx;
        float sc = g_scale[o], sh = g_shift[o];
#pragma unroll
        for (int q = 0; q < 4; q++) {
            int n = n0 + ty + 8*q;
            float v = g_y[(size_t)(b*NPTS + n)*OUTC + o];
            sT[ty+8*q][tx] = fmaxf(fmaf(v, sc, sh), 0.f);
        }
    }
    __syncthreads();
#pragma unroll
    for (int q = 0; q < 4; q++) {
        int o = o0 + ty + 8*q;
        out[((size_t)b*OUTC + o)*NPTS + n0 + tx] = sT[tx][ty+8*q];
    }
}

// ---------------- launch -----------------------------------------------------
extern "C" void kernel_launch(void* const* d_in, const int* in_sizes, int n_in,
                              void* d_out, int out_size) {
    const float* x     = (const float*)d_in[0];
    const float* w     = (const float*)d_in[1];
    const float* bias  = (const float*)d_in[2];
    const float* gamma = (const float*)d_in[3];
    const float* beta  = (const float*)d_in[4];
    float* out = (float*)d_out;

    // 61056 B dynamic smem for k_knn_feat (> 48KB default opt-in)
    cudaFuncSetAttribute(k_knn_feat, cudaFuncAttributeMaxDynamicSharedMemorySize, 61056);

    k_transpose<<<dim3(98, 6, 8), dim3(32, 8)>>>(x);
    k_x2<<<3136, 256>>>();
    k_knn_feat<<<dim3(98, 8), 256, 61056>>>(x);
    k_gemm<<<dim3(196, 6), 256>>>(w, bias);
    k_stats<<<1, OUTC>>>(gamma, beta);
    k_out<<<dim3(98, 12, 8), dim3(32, 8)>>>(out);
}